// round 12
// baseline (speedup 1.0000x reference)
#include <cuda_runtime.h>
#include <math.h>
#include <float.h>

#define Nn   2048
#define DIN  256
#define DIM  256
#define NH   8
#define CH   32
#define TOPK 16
#define ROWS 8
#define CHUNK 512
#define KP   33   // padded pitch for K/V/Q staging

// ---------------- device scratch (static, allocation-free) ----------------
__device__ float g_x[Nn * DIN];                 // LN1 output
__device__ float g_qkv[Nn * 3 * DIM];           // qkv, row-major [N][768]
__device__ float g_msg[Nn * DIM];               // attention message
__device__ float g_msg2[Nn * DIM];              // after proj + residual

// smem layout (floats): Ssh[8][2048] | Am[8][2048] | Kst[512][33] | Qs[8][33] | pad[8][128]
#define OFF_AM   16384
#define OFF_KST  32768
#define OFF_QS   49664
#define OFF_PAD  49928
#define SM_FLOATS 50952
#define SM_BYTES  (SM_FLOATS * 4)

__device__ __forceinline__ float warpMax(float v) {
    #pragma unroll
    for (int o = 16; o > 0; o >>= 1) v = fmaxf(v, __shfl_xor_sync(0xffffffffu, v, o));
    return v;
}
__device__ __forceinline__ float warpSum(float v) {
    #pragma unroll
    for (int o = 16; o > 0; o >>= 1) v += __shfl_xor_sync(0xffffffffu, v, o);
    return v;
}

// ---------------- LayerNorm (one block per row, 256 cols) ----------------
__global__ void ln_kernel(const float* __restrict__ in,
                          const float* __restrict__ w,
                          const float* __restrict__ b,
                          float* __restrict__ out) {
    __shared__ float red[256];
    int row = blockIdx.x, t = threadIdx.x;
    float v = in[row * 256 + t];
    red[t] = v; __syncthreads();
    for (int s = 128; s > 0; s >>= 1) { if (t < s) red[t] += red[t + s]; __syncthreads(); }
    float mu = red[0] * (1.0f / 256.0f);
    __syncthreads();
    float d = v - mu;
    red[t] = d * d; __syncthreads();
    for (int s = 128; s > 0; s >>= 1) { if (t < s) red[t] += red[t + s]; __syncthreads(); }
    float var = red[0] * (1.0f / 256.0f);
    out[row * 256 + t] = d * rsqrtf(var + 1e-5f) * w[t] + b[t];
}

// ---------------- SGEMM: C[M,NC] = A[M,K] @ B[K,NC] (64x64 tile) ----------
__global__ void sgemm_qkv(const float* __restrict__ A, const float* __restrict__ B,
                          float* __restrict__ C, int M, int K, int NC) {
    __shared__ float As[16][64];
    __shared__ float Bs[16][64];
    int tid = threadIdx.x;
    int tx = tid % 16, ty = tid / 16;
    int m0 = blockIdx.y * 64, n0 = blockIdx.x * 64;
    float acc[4][4] = {};
    for (int k0 = 0; k0 < K; k0 += 16) {
        for (int i = tid; i < 64 * 16; i += 256) {
            int m = i / 16, k = i % 16;
            As[k][m] = A[(size_t)(m0 + m) * K + k0 + k];
        }
        for (int i = tid; i < 16 * 64; i += 256) {
            int k = i / 64, n = i % 64;
            Bs[k][n] = B[(size_t)(k0 + k) * NC + n0 + n];
        }
        __syncthreads();
        #pragma unroll
        for (int k = 0; k < 16; k++) {
            float a[4], bb[4];
            #pragma unroll
            for (int i = 0; i < 4; i++) a[i] = As[k][ty * 4 + i];
            #pragma unroll
            for (int j = 0; j < 4; j++) bb[j] = Bs[k][tx * 4 + j];
            #pragma unroll
            for (int i = 0; i < 4; i++)
                #pragma unroll
                for (int j = 0; j < 4; j++) acc[i][j] += a[i] * bb[j];
        }
        __syncthreads();
    }
    for (int i = 0; i < 4; i++)
        for (int j = 0; j < 4; j++)
            C[(size_t)(m0 + ty * 4 + i) * NC + n0 + tx * 4 + j] = acc[i][j];
}

// ---------------- proj GEMM with bias + residual(v) epilogue --------------
__global__ void sgemm_proj(const float* __restrict__ A, const float* __restrict__ B,
                           const float* __restrict__ bias, const float* __restrict__ qkv,
                           float* __restrict__ C) {
    __shared__ float As[16][64];
    __shared__ float Bs[16][64];
    int tid = threadIdx.x;
    int tx = tid % 16, ty = tid / 16;
    int m0 = blockIdx.y * 64, n0 = blockIdx.x * 64;
    float acc[4][4] = {};
    for (int k0 = 0; k0 < 256; k0 += 16) {
        for (int i = tid; i < 64 * 16; i += 256) {
            int m = i / 16, k = i % 16;
            As[k][m] = A[(m0 + m) * 256 + k0 + k];
        }
        for (int i = tid; i < 16 * 64; i += 256) {
            int k = i / 64, n = i % 64;
            Bs[k][n] = B[(k0 + k) * 256 + n0 + n];
        }
        __syncthreads();
        #pragma unroll
        for (int k = 0; k < 16; k++) {
            float a[4], bb[4];
            #pragma unroll
            for (int i = 0; i < 4; i++) a[i] = As[k][ty * 4 + i];
            #pragma unroll
            for (int j = 0; j < 4; j++) bb[j] = Bs[k][tx * 4 + j];
            #pragma unroll
            for (int i = 0; i < 4; i++)
                #pragma unroll
                for (int j = 0; j < 4; j++) acc[i][j] += a[i] * bb[j];
        }
        __syncthreads();
    }
    for (int i = 0; i < 4; i++)
        for (int j = 0; j < 4; j++) {
            int m = m0 + ty * 4 + i, n = n0 + tx * 4 + j;
            C[m * 256 + n] = acc[i][j] + bias[n] + qkv[m * 768 + 512 + n];
        }
}

// ======= fused attention: QK^T -> softmax -> head-mean -> AV -> topk =======
// grid = 256 CTAs (8 query rows each), block = 256 threads (8 warps).
// S and A live entirely in smem; K/V streamed from L2. A never hits DRAM.
__global__ void __launch_bounds__(256) fused_attn(const float* __restrict__ qkv,
                                                  float* __restrict__ msg,
                                                  float* __restrict__ out_idx) {
    extern __shared__ float sh[];
    float* Ssh = sh;            // [8][2048]  scores -> exp values
    float* Am  = sh + OFF_AM;   // [8][2048]  fp32 head-mean accumulator
    float* Kst = sh + OFF_KST;  // [512][33]  K/V chunk staging
    float* Qs  = sh + OFF_QS;   // [8][33]
    float* pad = sh + OFF_PAD;  // [8][128]   AV partial sums

    int t = threadIdx.x;
    int lane = t & 31, w = t >> 5;
    int l0 = blockIdx.x * ROWS;

    int cqk = t & 127;   // QK: column within 128-col group
    int gq  = t >> 7;    // QK: row group (0/1) -> rows gq*4..gq*4+3
    int gav = w >> 2;    // AV: row group (0/1)
    int qav = w & 3;     // AV: s-quarter within chunk

    // zero head-mean accumulator
    for (int i = t; i < ROWS * 2048; i += 256) Am[i] = 0.0f;
    __syncthreads();

    for (int h = 0; h < NH; h++) {
        // ---- stage Q (8 rows x 32) ----
        Qs[(t >> 5) * KP + (t & 31)] = qkv[(size_t)(l0 + (t >> 5)) * 768 + h * 32 + (t & 31)];
        __syncthreads();
        float q[4][32];
        #pragma unroll
        for (int i = 0; i < 4; i++)
            #pragma unroll
            for (int d = 0; d < 32; d++)
                q[i][d] = Qs[(gq * 4 + i) * KP + d];

        // ---- QK phase: S[8][2048] in smem ----
        for (int s0 = 0; s0 < Nn; s0 += CHUNK) {
            for (int idx = t; idx < CHUNK * 8; idx += 256) {
                int j = idx >> 3, d4 = idx & 7;
                float4 v = *(const float4*)(qkv + (size_t)(s0 + j) * 768 + 256 + h * 32 + d4 * 4);
                float* dst = Kst + j * KP + d4 * 4;
                dst[0] = v.x; dst[1] = v.y; dst[2] = v.z; dst[3] = v.w;
            }
            __syncthreads();
            float acc[4][4] = {};
            #pragma unroll
            for (int d = 0; d < 32; d++) {
                float k0 = Kst[(cqk      ) * KP + d];
                float k1 = Kst[(cqk + 128) * KP + d];
                float k2 = Kst[(cqk + 256) * KP + d];
                float k3 = Kst[(cqk + 384) * KP + d];
                #pragma unroll
                for (int i = 0; i < 4; i++) {
                    acc[i][0] += q[i][d] * k0;
                    acc[i][1] += q[i][d] * k1;
                    acc[i][2] += q[i][d] * k2;
                    acc[i][3] += q[i][d] * k3;
                }
            }
            const float SC = 0.1767766952966369f; // 1/sqrt(32)
            #pragma unroll
            for (int i = 0; i < 4; i++)
                #pragma unroll
                for (int cc = 0; cc < 4; cc++)
                    Ssh[(gq * 4 + i) * 2048 + s0 + cc * 128 + cqk] = acc[i][cc] * SC;
            __syncthreads();
        }

        // ---- softmax: warp w owns row w; store exp(v-mx); Am += A/8 ----
        float iv;  // 1/sum, live into msg write (r == w there)
        {
            float* row = Ssh + w * 2048;
            float mx = -FLT_MAX;
            #pragma unroll 8
            for (int k = 0; k < 64; k++) mx = fmaxf(mx, row[lane + (k << 5)]);
            mx = warpMax(mx);
            float sum = 0.0f;
            #pragma unroll 8
            for (int k = 0; k < 64; k++) {
                float e = __expf(row[lane + (k << 5)] - mx);
                row[lane + (k << 5)] = e;
                sum += e;
            }
            sum = warpSum(sum);
            iv = 1.0f / sum;
            float ivc = iv * 0.125f;
            float* am = Am + w * 2048;
            #pragma unroll 8
            for (int k = 0; k < 64; k++)
                am[lane + (k << 5)] += row[lane + (k << 5)] * ivc;
        }
        __syncthreads();

        // ---- AV phase: warp = (rowgroup gav, s-quarter qav), lane = dv ----
        float av[4] = {0.f, 0.f, 0.f, 0.f};
        for (int s0 = 0; s0 < Nn; s0 += CHUNK) {
            for (int idx = t; idx < CHUNK * 8; idx += 256) {
                int j = idx >> 3, d4 = idx & 7;
                float4 v = *(const float4*)(qkv + (size_t)(s0 + j) * 768 + 512 + h * 32 + d4 * 4);
                float* dst = Kst + j * KP + d4 * 4;
                dst[0] = v.x; dst[1] = v.y; dst[2] = v.z; dst[3] = v.w;
            }
            __syncthreads();
            int jb = qav * 128;
            #pragma unroll 4
            for (int jj = 0; jj < 128; jj++) {
                int j = jb + jj;
                float v = Kst[j * KP + lane];
                int s = s0 + j;
                #pragma unroll
                for (int i = 0; i < 4; i++)
                    av[i] += Ssh[(gav * 4 + i) * 2048 + s] * v;
            }
            __syncthreads();
        }
        #pragma unroll
        for (int i = 0; i < 4; i++)
            pad[w * 128 + i * 32 + lane] = av[i];
        __syncthreads();
        // reduce 4 s-quarters, apply 1/sum, write message (r == w for this thread)
        {
            int r = t >> 5, dv = t & 31;
            int g = r >> 2, ri = r & 3;
            float s = pad[(g * 4 + 0) * 128 + ri * 32 + dv]
                    + pad[(g * 4 + 1) * 128 + ri * 32 + dv]
                    + pad[(g * 4 + 2) * 128 + ri * 32 + dv]
                    + pad[(g * 4 + 3) * 128 + ri * 32 + dv];
            msg[(size_t)(l0 + r) * 256 + h * 32 + dv] = s * iv;
        }
        __syncthreads();
    }

    // ---- top-16 per row on fp32 Am (warp w owns row w) ----
    {
        float* am = Am + w * 2048;
        for (int sel = 0; sel < TOPK; sel++) {
            float bv = -FLT_MAX; int bi = 1 << 30;
            #pragma unroll 8
            for (int k = 0; k < 64; k++) {
                int c = lane + (k << 5);
                float v = am[c];
                if (v > bv || (v == bv && c < bi)) { bv = v; bi = c; }
            }
            #pragma unroll
            for (int o = 16; o > 0; o >>= 1) {
                float ov = __shfl_xor_sync(0xffffffffu, bv, o);
                int   oi = __shfl_xor_sync(0xffffffffu, bi, o);
                if (ov > bv || (ov == bv && oi < bi)) { bv = ov; bi = oi; }
            }
            if (lane == 0) {
                out_idx[(l0 + w) * TOPK + sel] = (float)bi;
                am[bi] = -FLT_MAX;
            }
            __syncwarp();
        }
    }
}

// ---------------- launch ----------------------------------------------------
extern "C" void kernel_launch(void* const* d_in, const int* in_sizes, int n_in,
                              void* d_out, int out_size) {
    const float* point  = (const float*)d_in[0];
    const float* w_qkv  = (const float*)d_in[1];
    const float* w_proj = (const float*)d_in[2];
    const float* b_proj = (const float*)d_in[3];
    const float* n1w    = (const float*)d_in[4];
    const float* n1b    = (const float*)d_in[5];
    const float* n2w    = (const float*)d_in[6];
    const float* n2b    = (const float*)d_in[7];
    float* out = (float*)d_out;

    float *p_x, *p_qkv, *p_msg, *p_msg2;
    cudaGetSymbolAddress((void**)&p_x,    g_x);
    cudaGetSymbolAddress((void**)&p_qkv,  g_qkv);
    cudaGetSymbolAddress((void**)&p_msg,  g_msg);
    cudaGetSymbolAddress((void**)&p_msg2, g_msg2);

    // unconditional (no static guards): cheap, deterministic, capture-safe
    cudaFuncSetAttribute(fused_attn, cudaFuncAttributeMaxDynamicSharedMemorySize, SM_BYTES);

    // 1. LN1
    ln_kernel<<<Nn, 256>>>(point, n1w, n1b, p_x);
    // 2. QKV GEMM: [2048,256] @ [256,768]
    sgemm_qkv<<<dim3(768 / 64, Nn / 64), 256>>>(p_x, w_qkv, p_qkv, Nn, 256, 768);
    // 3. fused attention (+ topk indices region of d_out)
    fused_attn<<<Nn / ROWS, 256, SM_BYTES>>>(p_qkv, p_msg, out + Nn * DIM);
    // 4. proj + bias + residual(v)
    sgemm_proj<<<dim3(256 / 64, Nn / 64), 256>>>(p_msg, w_proj, b_proj, p_qkv, p_msg2);
    // 5. LN2 -> main output region
    ln_kernel<<<Nn, 256>>>(p_msg2, n2w, n2b, out);
}

// round 14
// speedup vs baseline: 2.1641x; 2.1641x over previous
#include <cuda_runtime.h>
#include <math.h>
#include <float.h>

#define Nn   2048
#define DIN  256
#define DIM  256
#define NH   8
#define CH   32
#define TOPK 16

// ---------------- device scratch (static, allocation-free) ----------------
__device__ float g_x[Nn * DIN];                 // LN1 output
__device__ float g_qkv[Nn * 3 * DIM];           // qkv, row-major [N][768]
__device__ float g_S[(size_t)NH * Nn * Nn];     // per-head scores -> A (128 MB)
__device__ float g_msg[Nn * DIM];               // attention message
__device__ float g_msg2[Nn * DIM];              // after proj + residual

__device__ __forceinline__ float warpMax(float v) {
    #pragma unroll
    for (int o = 16; o > 0; o >>= 1) v = fmaxf(v, __shfl_xor_sync(0xffffffffu, v, o));
    return v;
}
__device__ __forceinline__ float warpSum(float v) {
    #pragma unroll
    for (int o = 16; o > 0; o >>= 1) v += __shfl_xor_sync(0xffffffffu, v, o);
    return v;
}

// ---------------- LayerNorm (one block per row, 256 cols) ----------------
__global__ void ln_kernel(const float* __restrict__ in,
                          const float* __restrict__ w,
                          const float* __restrict__ b,
                          float* __restrict__ out) {
    __shared__ float red[256];
    int row = blockIdx.x, t = threadIdx.x;
    float v = in[row * 256 + t];
    red[t] = v; __syncthreads();
    for (int s = 128; s > 0; s >>= 1) { if (t < s) red[t] += red[t + s]; __syncthreads(); }
    float mu = red[0] * (1.0f / 256.0f);
    __syncthreads();
    float d = v - mu;
    red[t] = d * d; __syncthreads();
    for (int s = 128; s > 0; s >>= 1) { if (t < s) red[t] += red[t + s]; __syncthreads(); }
    float var = red[0] * (1.0f / 256.0f);
    out[row * 256 + t] = d * rsqrtf(var + 1e-5f) * w[t] + b[t];
}

// ------- SGEMM 32x64 tile, micro 1x8, B broadcast float4 (high occ) -------
__global__ void __launch_bounds__(256) sgemm32(const float* __restrict__ A,
                                               const float* __restrict__ B,
                                               float* __restrict__ C,
                                               int K, int NC) {
    __shared__ float As[16][33];
    __shared__ float Bs[16][64];
    int t = threadIdx.x;
    int r = t & 31, c8 = t >> 5;
    int m0 = blockIdx.y * 32, n0 = blockIdx.x * 64;
    float acc[8] = {};
    for (int k0 = 0; k0 < K; k0 += 16) {
        { // As: 32m x 16k (2 elems/thread)
            int m = t >> 4, k = t & 15;
            As[k][m]      = A[(size_t)(m0 + m) * K + k0 + k];
            As[k][m + 16] = A[(size_t)(m0 + m + 16) * K + k0 + k];
        }
        { // Bs: 16k x 64n via float4 (1/thread)
            int k = t >> 4, nq = t & 15;
            float4 b4 = *(const float4*)(B + (size_t)(k0 + k) * NC + n0 + nq * 4);
            *(float4*)&Bs[k][nq * 4] = b4;
        }
        __syncthreads();
        #pragma unroll
        for (int k = 0; k < 16; k++) {
            float a = As[k][r];
            float4 b0 = *(const float4*)&Bs[k][c8 * 8];
            float4 b1 = *(const float4*)&Bs[k][c8 * 8 + 4];
            acc[0] += a * b0.x; acc[1] += a * b0.y; acc[2] += a * b0.z; acc[3] += a * b0.w;
            acc[4] += a * b1.x; acc[5] += a * b1.y; acc[6] += a * b1.z; acc[7] += a * b1.w;
        }
        __syncthreads();
    }
    float* cp = C + (size_t)(m0 + r) * NC + n0 + c8 * 8;
    *(float4*)cp       = make_float4(acc[0], acc[1], acc[2], acc[3]);
    *(float4*)(cp + 4) = make_float4(acc[4], acc[5], acc[6], acc[7]);
}

// ------- proj variant: + bias + residual(v from qkv) ----------------------
__global__ void __launch_bounds__(256) sgemm32_proj(const float* __restrict__ A,
                                                    const float* __restrict__ B,
                                                    const float* __restrict__ bias,
                                                    const float* __restrict__ qkv,
                                                    float* __restrict__ C) {
    const int K = 256, NC = 256;
    __shared__ float As[16][33];
    __shared__ float Bs[16][64];
    int t = threadIdx.x;
    int r = t & 31, c8 = t >> 5;
    int m0 = blockIdx.y * 32, n0 = blockIdx.x * 64;
    float acc[8] = {};
    for (int k0 = 0; k0 < K; k0 += 16) {
        {
            int m = t >> 4, k = t & 15;
            As[k][m]      = A[(size_t)(m0 + m) * K + k0 + k];
            As[k][m + 16] = A[(size_t)(m0 + m + 16) * K + k0 + k];
        }
        {
            int k = t >> 4, nq = t & 15;
            float4 b4 = *(const float4*)(B + (size_t)(k0 + k) * NC + n0 + nq * 4);
            *(float4*)&Bs[k][nq * 4] = b4;
        }
        __syncthreads();
        #pragma unroll
        for (int k = 0; k < 16; k++) {
            float a = As[k][r];
            float4 b0 = *(const float4*)&Bs[k][c8 * 8];
            float4 b1 = *(const float4*)&Bs[k][c8 * 8 + 4];
            acc[0] += a * b0.x; acc[1] += a * b0.y; acc[2] += a * b0.z; acc[3] += a * b0.w;
            acc[4] += a * b1.x; acc[5] += a * b1.y; acc[6] += a * b1.z; acc[7] += a * b1.w;
        }
        __syncthreads();
    }
    int m = m0 + r, n = n0 + c8 * 8;
    float4 bi0 = *(const float4*)(bias + n);
    float4 bi1 = *(const float4*)(bias + n + 4);
    float4 rv0 = *(const float4*)(qkv + (size_t)m * 768 + 512 + n);
    float4 rv1 = *(const float4*)(qkv + (size_t)m * 768 + 512 + n + 4);
    float* cp = C + (size_t)m * 256 + n;
    *(float4*)cp       = make_float4(acc[0] + bi0.x + rv0.x, acc[1] + bi0.y + rv0.y,
                                     acc[2] + bi0.z + rv0.z, acc[3] + bi0.w + rv0.w);
    *(float4*)(cp + 4) = make_float4(acc[4] + bi1.x + rv1.x, acc[5] + bi1.y + rv1.y,
                                     acc[6] + bi1.z + rv1.z, acc[7] + bi1.w + rv1.w);
}

// ---------------- per-head QK^T * scale -> g_S (128x128 tiles) ------------
__global__ void __launch_bounds__(256) qk_kernel(const float* __restrict__ qkv) {
    __shared__ float Qs[128][33];
    __shared__ float Ks[128][33];
    int t = threadIdx.x;
    int h = blockIdx.z;
    int l0 = blockIdx.y * 128, s0 = blockIdx.x * 128;
    for (int i = t; i < 128 * 32; i += 256) {
        int r = i >> 5, d = i & 31;
        Qs[r][d] = qkv[(size_t)(l0 + r) * 768 + h * 32 + d];
        Ks[r][d] = qkv[(size_t)(s0 + r) * 768 + 256 + h * 32 + d];
    }
    __syncthreads();
    int tx = t & 15, ty = t >> 4;
    float acc[8][8] = {};
    #pragma unroll
    for (int d = 0; d < 32; d++) {
        float a[8], b[8];
        #pragma unroll
        for (int i = 0; i < 8; i++) a[i] = Qs[ty + i * 16][d];
        #pragma unroll
        for (int j = 0; j < 8; j++) b[j] = Ks[tx + j * 16][d];
        #pragma unroll
        for (int i = 0; i < 8; i++)
            #pragma unroll
            for (int j = 0; j < 8; j++) acc[i][j] += a[i] * b[j];
    }
    const float scale = 0.1767766952966369f; // 1/sqrt(32)
    float* Sp = g_S + ((size_t)h * Nn + l0) * Nn + s0;
    #pragma unroll
    for (int i = 0; i < 8; i++)
        #pragma unroll
        for (int j = 0; j < 8; j++)
            Sp[(size_t)(ty + i * 16) * Nn + tx + j * 16] = acc[i][j] * scale;
}

// ------- fused: softmax (8 heads of row l) + head-mean + top-16 -----------
__global__ void __launch_bounds__(256) softmax_mean_topk(float* __restrict__ out_idx) {
    __shared__ float am[2048];
    __shared__ float red[8];
    __shared__ float sv[8];
    __shared__ int   si[8];
    int l = blockIdx.x, t = threadIdx.x;
    int lane = t & 31, w = t >> 5;
    float amv[8] = {0, 0, 0, 0, 0, 0, 0, 0};

    for (int h = 0; h < NH; h++) {
        float* row = g_S + ((size_t)h * Nn + l) * Nn;
        float4 v0 = *(const float4*)(row + t * 8);
        float4 v1 = *(const float4*)(row + t * 8 + 4);
        float vals[8] = {v0.x, v0.y, v0.z, v0.w, v1.x, v1.y, v1.z, v1.w};
        float mx = vals[0];
        #pragma unroll
        for (int i = 1; i < 8; i++) mx = fmaxf(mx, vals[i]);
        mx = warpMax(mx);
        if (lane == 0) red[w] = mx;
        __syncthreads();
        mx = red[0];
        #pragma unroll
        for (int i = 1; i < 8; i++) mx = fmaxf(mx, red[i]);
        __syncthreads();
        float sum = 0.0f;
        #pragma unroll
        for (int i = 0; i < 8; i++) { vals[i] = __expf(vals[i] - mx); sum += vals[i]; }
        sum = warpSum(sum);
        if (lane == 0) red[w] = sum;
        __syncthreads();
        sum = red[0];
        #pragma unroll
        for (int i = 1; i < 8; i++) sum += red[i];
        __syncthreads();
        float inv = 1.0f / sum;
        #pragma unroll
        for (int i = 0; i < 8; i++) { vals[i] *= inv; amv[i] += vals[i]; }
        *(float4*)(row + t * 8)     = make_float4(vals[0], vals[1], vals[2], vals[3]);
        *(float4*)(row + t * 8 + 4) = make_float4(vals[4], vals[5], vals[6], vals[7]);
    }
    #pragma unroll
    for (int i = 0; i < 8; i++) am[t * 8 + i] = amv[i] * 0.125f;
    __syncthreads();

    // top-16, ties -> lowest index (matches jax.lax.top_k)
    for (int sel = 0; sel < TOPK; sel++) {
        float bv = -FLT_MAX; int bi = 1 << 30;
        #pragma unroll
        for (int i = 0; i < 8; i++) {
            int c = t * 8 + i;
            float v = am[c];
            if (v > bv || (v == bv && c < bi)) { bv = v; bi = c; }
        }
        #pragma unroll
        for (int o = 16; o > 0; o >>= 1) {
            float ov = __shfl_xor_sync(0xffffffffu, bv, o);
            int   oi = __shfl_xor_sync(0xffffffffu, bi, o);
            if (ov > bv || (ov == bv && oi < bi)) { bv = ov; bi = oi; }
        }
        if (lane == 0) { sv[w] = bv; si[w] = bi; }
        __syncthreads();
        if (w == 0) {
            float v2 = (lane < 8) ? sv[lane] : -FLT_MAX;
            int   i2 = (lane < 8) ? si[lane] : (1 << 30);
            #pragma unroll
            for (int o = 4; o > 0; o >>= 1) {
                float ov = __shfl_xor_sync(0xffffffffu, v2, o);
                int   oi = __shfl_xor_sync(0xffffffffu, i2, o);
                if (ov > v2 || (ov == v2 && oi < i2)) { v2 = ov; i2 = oi; }
            }
            if (lane == 0) {
                out_idx[l * TOPK + sel] = (float)i2;
                am[i2] = -FLT_MAX;
            }
        }
        __syncthreads();
    }
}

// ---------------- A @ V: 64l x 32d tile, micro 1x8, FMA-bound -------------
#define AST_P 65
#define VST_P 36
#define AV_SMEM_FLOATS (128 * AST_P + 128 * VST_P)
#define AV_SMEM_BYTES  (AV_SMEM_FLOATS * 4)

__global__ void __launch_bounds__(256) av_kernel(const float* __restrict__ qkv,
                                                 float* __restrict__ msg) {
    extern __shared__ float sh[];
    float* Ast = sh;                 // [k=128][l=64], pitch 65 (conflict-free scalar reads)
    float* Vst = sh + 128 * AST_P;   // [k=128][d=32], pitch 36 (float4-aligned broadcast reads)
    int t = threadIdx.x;
    int l = t & 63, dg = t >> 6;     // 64 rows x 4 d-groups (8 d each)
    int h = blockIdx.y, l0 = blockIdx.x * 64;
    float acc[8] = {};
    for (int s0 = 0; s0 < Nn; s0 += 128) {
        // stage A transposed: read g_S rows (coalesced float4), scatter to [k][l]
        for (int idx = t; idx < 64 * 32; idx += 256) {
            int r = idx >> 5, kq = idx & 31;
            float4 a4 = *(const float4*)(g_S + ((size_t)h * Nn + l0 + r) * Nn + s0 + kq * 4);
            Ast[(kq * 4 + 0) * AST_P + r] = a4.x;
            Ast[(kq * 4 + 1) * AST_P + r] = a4.y;
            Ast[(kq * 4 + 2) * AST_P + r] = a4.z;
            Ast[(kq * 4 + 3) * AST_P + r] = a4.w;
        }
        // stage V: [k][d]
        for (int idx = t; idx < 128 * 8; idx += 256) {
            int k = idx >> 3, dq = idx & 7;
            float4 v4 = *(const float4*)(qkv + (size_t)(s0 + k) * 768 + 512 + h * 32 + dq * 4);
            *(float4*)&Vst[k * VST_P + dq * 4] = v4;
        }
        __syncthreads();
        #pragma unroll 8
        for (int k = 0; k < 128; k++) {
            float a = Ast[k * AST_P + l];
            float4 v0 = *(const float4*)&Vst[k * VST_P + dg * 8];
            float4 v1 = *(const float4*)&Vst[k * VST_P + dg * 8 + 4];
            acc[0] += a * v0.x; acc[1] += a * v0.y; acc[2] += a * v0.z; acc[3] += a * v0.w;
            acc[4] += a * v1.x; acc[5] += a * v1.y; acc[6] += a * v1.z; acc[7] += a * v1.w;
        }
        __syncthreads();
    }
    float* mp = msg + (size_t)(l0 + l) * 256 + h * 32 + dg * 8;
    *(float4*)mp       = make_float4(acc[0], acc[1], acc[2], acc[3]);
    *(float4*)(mp + 4) = make_float4(acc[4], acc[5], acc[6], acc[7]);
}

// ---------------- launch ----------------------------------------------------
extern "C" void kernel_launch(void* const* d_in, const int* in_sizes, int n_in,
                              void* d_out, int out_size) {
    const float* point  = (const float*)d_in[0];
    const float* w_qkv  = (const float*)d_in[1];
    const float* w_proj = (const float*)d_in[2];
    const float* b_proj = (const float*)d_in[3];
    const float* n1w    = (const float*)d_in[4];
    const float* n1b    = (const float*)d_in[5];
    const float* n2w    = (const float*)d_in[6];
    const float* n2b    = (const float*)d_in[7];
    float* out = (float*)d_out;

    float *p_x, *p_qkv, *p_msg, *p_msg2;
    cudaGetSymbolAddress((void**)&p_x,    g_x);
    cudaGetSymbolAddress((void**)&p_qkv,  g_qkv);
    cudaGetSymbolAddress((void**)&p_msg,  g_msg);
    cudaGetSymbolAddress((void**)&p_msg2, g_msg2);

    // unconditional (no static guards): deterministic, capture-safe
    cudaFuncSetAttribute(av_kernel, cudaFuncAttributeMaxDynamicSharedMemorySize, AV_SMEM_BYTES);

    // 1. LN1
    ln_kernel<<<Nn, 256>>>(point, n1w, n1b, p_x);
    // 2. QKV GEMM: [2048,256] @ [256,768]
    sgemm32<<<dim3(768 / 64, Nn / 32), 256>>>(p_x, w_qkv, p_qkv, 256, 768);
    // 3. per-head scores (128x128 tiles)
    qk_kernel<<<dim3(Nn / 128, Nn / 128, NH), 256>>>(p_qkv);
    // 4. fused softmax + head-mean + top-16 (indices region of d_out)
    softmax_mean_topk<<<Nn, 256>>>(out + Nn * DIM);
    // 5. A @ V
    av_kernel<<<dim3(Nn / 64, NH), 256, AV_SMEM_BYTES>>>(p_qkv, p_msg);
    // 6. proj + bias + residual(v)
    sgemm32_proj<<<dim3(256 / 64, Nn / 32), 256>>>(p_msg, w_proj, b_proj, p_qkv, p_msg2);
    // 7. LN2 -> main output region
    ln_kernel<<<Nn, 256>>>(p_msg2, n2w, n2b, out);
}